// round 10
// baseline (speedup 1.0000x reference)
#include <cuda_runtime.h>

// ---------------------------------------------------------------------------
// Causal spectral filter: out = irfft(rfft(x,16384) * spec)[..., :8192, :]
// 8192-pt complex FFT [8,8,8,8,2], in-place smem, 512 threads.
// k_conv: pointwise filter fused into the s4 turnaround (register-staged).
// float4 transposes. 2 blocks/SM, 64-reg budget.
// ---------------------------------------------------------------------------

#define IDX(i) ((i) + ((i) >> 4))     // smem pad: conflict-free for all strides

static __device__ float  g_xt[8u * 512u * 8192u];   // x transposed (B,D,N)
static __device__ float  g_yt[8u * 512u * 8192u];   // y transposed (B,D,N)
static __device__ float2 g_spec[512u * 8200u];      // per-channel spectrum (natural k)
static __device__ float2 g_tw[1024];                // W_8192^c, c<1024

__device__ __forceinline__ float2 cadd(float2 a, float2 b) { return make_float2(a.x + b.x, a.y + b.y); }
__device__ __forceinline__ float2 csub(float2 a, float2 b) { return make_float2(a.x - b.x, a.y - b.y); }
__device__ __forceinline__ float2 cmul(float2 a, float2 b) {
    return make_float2(fmaf(a.x, b.x, -a.y * b.y), fmaf(a.x, b.y, a.y * b.x));
}
__device__ __forceinline__ float2 cmulc(float2 a, float2 b) {   // a * conj(b)
    return make_float2(fmaf(a.x, b.x,  a.y * b.y), fmaf(a.y, b.x, -a.x * b.y));
}
template <int S>
__device__ __forceinline__ float2 crot(float2 z) {   // multiply by S*i
    return (S < 0) ? make_float2(z.y, -z.x) : make_float2(-z.y, z.x);
}

// digit-reverse for radices [8,8,8,8,2]: pos of coefficient k after fwd FFT
__device__ __forceinline__ int drev(int k) {
    return ((k & 7) << 10) | (((k >> 3) & 7) << 7) | (((k >> 6) & 7) << 4)
         | (((k >> 9) & 7) << 1) | ((k >> 12) & 1);
}
// 3-digit base-8 reverse of a 9-bit value
__device__ __forceinline__ int rev9(int g) {
    return ((g & 7) << 6) | (g & 56) | ((g >> 6) & 7);
}

// W_16384^k for 0<=k<8192 from the 1024-entry table
__device__ __forceinline__ float2 tw16384(const float2* T, int k) {
    int a = k >> 1;
    float2 w = T[a & 1023];
    int u = (a >> 10) & 3;
    const float S2 = 0.70710678118654752f;
    if (u & 2) w = make_float2(w.y, -w.x);
    if (u & 1) w = cmul(w, make_float2(S2, -S2));
    if (k & 1) w = cmul(w, make_float2(0.99999992646571789f, -3.8349518757139556e-4f));
    return w;
}

template <int SGN>
__device__ __forceinline__ void bfly8(float2 a[8]) {
    const float C0 = 0.70710678118654752f;
    const float2 w81 = make_float2(C0, SGN * C0);
    const float2 w83 = make_float2(-C0, SGN * C0);
    float2 t0 = cadd(a[0], a[4]), t4 = csub(a[0], a[4]);
    float2 t1 = cadd(a[1], a[5]), t5 = csub(a[1], a[5]);
    float2 t2 = cadd(a[2], a[6]), t6 = csub(a[2], a[6]);
    float2 t3 = cadd(a[3], a[7]), t7 = csub(a[3], a[7]);
    float2 E0 = cadd(t0, t2), E2 = csub(t0, t2);
    float2 r6 = crot<SGN>(t6);
    float2 E1 = cadd(t4, r6), E3 = csub(t4, r6);
    float2 O0 = cadd(t1, t3), O2 = csub(t1, t3);
    float2 r7 = crot<SGN>(t7);
    float2 O1 = cadd(t5, r7), O3 = csub(t5, r7);
    float2 m1 = cmul(O1, w81);
    float2 m2 = crot<SGN>(O2);
    float2 m3 = cmul(O3, w83);
    a[0] = cadd(E0, O0); a[4] = csub(E0, O0);
    a[1] = cadd(E1, m1); a[5] = csub(E1, m1);
    a[2] = cadd(E2, m2); a[6] = csub(E2, m2);
    a[3] = cadd(E3, m3); a[7] = csub(E3, m3);
}

// radix-8 butterfly with a[4..7] known zero (only a[0..3] read)
template <int SGN>
__device__ __forceinline__ void bfly8hz(float2 a[8]) {
    const float C0 = 0.70710678118654752f;
    const float2 w81 = make_float2(C0, SGN * C0);
    const float2 w83 = make_float2(-C0, SGN * C0);
    float2 E0 = cadd(a[0], a[2]), E2 = csub(a[0], a[2]);
    float2 r6 = crot<SGN>(a[2]);
    float2 E1 = cadd(a[0], r6), E3 = csub(a[0], r6);
    float2 O0 = cadd(a[1], a[3]), O2 = csub(a[1], a[3]);
    float2 r7 = crot<SGN>(a[3]);
    float2 O1 = cadd(a[1], r7), O3 = csub(a[1], r7);
    float2 m1 = cmul(O1, w81);
    float2 m2 = crot<SGN>(O2);
    float2 m3 = cmul(O3, w83);
    a[0] = cadd(E0, O0); a[4] = csub(E0, O0);
    a[1] = cadd(E1, m1); a[5] = csub(E1, m1);
    a[2] = cadd(E2, m2); a[6] = csub(E2, m2);
    a[3] = cadd(E3, m3); a[7] = csub(E3, m3);
}

// store registers a[] twiddled to positions base + (r<<SH)
__device__ __forceinline__ void tw_store(float2* buf, float2 a[8], int base, int SH, float2 w1) {
    buf[IDX(base)] = a[0];
    float2 w = w1;
    buf[IDX(base + (1 << SH))] = cmul(a[1], w);
#pragma unroll
    for (int r = 2; r < 8; r++) { w = cmul(w, w1); buf[IDX(base + (r << SH))] = cmul(a[r], w); }
}

// ---- stage helpers (512 threads, 2 butterflies each, transient regs) ------

template <int L2S>
__device__ __forceinline__ void fwd_mid(float2* buf, const float2* T, int t) {
#pragma unroll
    for (int h = 0; h < 2; h++) {
        int b = t + (h << 9);
        int j = b & ((1 << L2S) - 1);
        int base = ((b >> L2S) << (L2S + 3)) + j;
        float2 a[8];
#pragma unroll
        for (int i = 0; i < 8; i++) a[i] = buf[IDX(base + (i << L2S))];
        bfly8<-1>(a);
        tw_store(buf, a, base, L2S, T[j << (10 - L2S)]);
    }
}

template <int L2S>
__device__ __forceinline__ void inv_mid(float2* buf, const float2* T, int t) {
#pragma unroll
    for (int h = 0; h < 2; h++) {
        int b = t + (h << 9);
        int j = b & ((1 << L2S) - 1);
        int base = ((b >> L2S) << (L2S + 3)) + j;
        float2 w1 = T[j << (10 - L2S)];
        float2 a[8];
        a[0] = buf[IDX(base)];
        float2 w = w1;
        a[1] = cmulc(buf[IDX(base + (1 << L2S))], w);
#pragma unroll
        for (int r = 2; r < 8; r++) { w = cmul(w, w1); a[r] = cmulc(buf[IDX(base + (r << L2S))], w); }
        bfly8<1>(a);
#pragma unroll
        for (int i = 0; i < 8; i++) buf[IDX(base + (i << L2S))] = a[i];
    }
}

// fwd stage4 + radix-2, fully in-thread (used by k_filter)
__device__ __forceinline__ void fwd_s4_r2(float2* buf, const float2* T, int t) {
    int base = t << 4;
    float2 e1[8];
#pragma unroll
    for (int i = 0; i < 8; i++) e1[i] = buf[IDX(base + 2 * i + 1)];
    bfly8<-1>(e1);
    {
        float2 w1 = T[512];
        float2 w = w1;
        e1[1] = cmul(e1[1], w);
#pragma unroll
        for (int r = 2; r < 8; r++) { w = cmul(w, w1); e1[r] = cmul(e1[r], w); }
    }
    float2 e0[8];
#pragma unroll
    for (int i = 0; i < 8; i++) e0[i] = buf[IDX(base + 2 * i)];
    bfly8<-1>(e0);
#pragma unroll
    for (int r = 0; r < 8; r++) {
        buf[IDX(base + 2 * r)]     = cadd(e0[r], e1[r]);
        buf[IDX(base + 2 * r + 1)] = csub(e0[r], e1[r]);
    }
}

// inverse radix-2 + stage4, fully in-thread (used by k_filter)
__device__ __forceinline__ void inv_s4_r2(float2* buf, const float2* T, int t) {
    int base = t << 4;
    float2 a[8], b[8];
#pragma unroll
    for (int r = 0; r < 8; r++) {
        float2 z0 = buf[IDX(base + 2 * r)];
        float2 z1 = buf[IDX(base + 2 * r + 1)];
        a[r] = cadd(z0, z1);
        b[r] = csub(z0, z1);
    }
    {
        float2 w1 = T[512];
        float2 w = w1;
        b[1] = cmulc(b[1], w);
#pragma unroll
        for (int r = 2; r < 8; r++) { w = cmul(w, w1); b[r] = cmulc(b[r], w); }
    }
    bfly8<1>(a);
    bfly8<1>(b);
#pragma unroll
    for (int r = 0; r < 8; r++) {
        buf[IDX(base + 2 * r)]     = a[r];
        buf[IDX(base + 2 * r + 1)] = b[r];
    }
}

// ---------------------------------------------------------------------------

__global__ void k_tw() {
    int j = blockIdx.x * blockDim.x + threadIdx.x;
    if (j < 1024) {
        double a = -2.0 * 3.14159265358979323846264338327950288 * (double)j / 8192.0;
        g_tw[j] = make_float2((float)cos(a), (float)sin(a));
    }
}

// x (B,N,D) -> g_xt (B,D,N), 64x64 tiles, float4 both gmem sides
__global__ void __launch_bounds__(256) k_tin(const float* __restrict__ x) {
    __shared__ float s[64][65];
    int b = blockIdx.z;
    int d0 = blockIdx.x << 6, n0 = blockIdx.y << 6;
    int tx = threadIdx.x, ty = threadIdx.y;
    const float* xb = x + (size_t)b * 8192u * 512u;
#pragma unroll
    for (int m = 0; m < 4; m++) {
        int n = n0 + ty + 16 * m;
        float4 v = *(const float4*)&xb[(size_t)n * 512u + d0 + 4 * tx];
        s[4 * tx + 0][ty + 16 * m] = v.x;
        s[4 * tx + 1][ty + 16 * m] = v.y;
        s[4 * tx + 2][ty + 16 * m] = v.z;
        s[4 * tx + 3][ty + 16 * m] = v.w;
    }
    __syncthreads();
    float* xt = g_xt + (size_t)b * 512u * 8192u;
#pragma unroll
    for (int m = 0; m < 4; m++) {
        int dl = ty + 16 * m;
        float4 w = make_float4(s[dl][4 * tx], s[dl][4 * tx + 1],
                               s[dl][4 * tx + 2], s[dl][4 * tx + 3]);
        *(float4*)&xt[(size_t)(d0 + dl) * 8192u + n0 + 4 * tx] = w;
    }
}

// g_yt (B,D,N) -> out (B,N,D), 64x64 tiles, float4 both gmem sides
__global__ void __launch_bounds__(256) k_tout(float* __restrict__ out) {
    __shared__ float s[64][65];
    int b = blockIdx.z;
    int d0 = blockIdx.x << 6, n0 = blockIdx.y << 6;
    int tx = threadIdx.x, ty = threadIdx.y;
    const float* yt = g_yt + (size_t)b * 512u * 8192u;
#pragma unroll
    for (int m = 0; m < 4; m++) {
        int dl = ty + 16 * m;
        float4 v = *(const float4*)&yt[(size_t)(d0 + dl) * 8192u + n0 + 4 * tx];
        s[4 * tx + 0][dl] = v.x;       // s[n_local][d_local]
        s[4 * tx + 1][dl] = v.y;
        s[4 * tx + 2][dl] = v.z;
        s[4 * tx + 3][dl] = v.w;
    }
    __syncthreads();
#pragma unroll
    for (int m = 0; m < 4; m++) {
        int nl = ty + 16 * m;
        float4 w = make_float4(s[nl][4 * tx], s[nl][4 * tx + 1],
                               s[nl][4 * tx + 2], s[nl][4 * tx + 3]);
        *(float4*)&out[((size_t)b * 8192u + n0 + nl) * 512u + d0 + 4 * tx] = w;
    }
}

// Per-channel spectrum build (R5 structure, unchanged)
__global__ void __launch_bounds__(512, 2) k_filter(const float* __restrict__ coeffs,
                                                   const float* __restrict__ dc) {
    extern __shared__ float2 sm[];
    float2* buf = sm;                       // 8704
    float2* T   = sm + 8704;                // 1024
    float*  cf  = (float*)(sm + 9728);      // 512 floats
    int d = blockIdx.x;
    int t = threadIdx.x;
    T[t] = g_tw[t];
    T[t + 512] = g_tw[t + 512];
    cf[t] = coeffs[d * 512 + t];
    float dcv = dc[d];
    __syncthreads();

    auto interp = [&](int k) -> float {
        if (k == 0) return dcv;
        float src = ((float)k - 0.5f) * 0.0625f - 0.5f;
        src = fminf(fmaxf(src, 0.0f), 511.0f);
        int lo = (int)src;
        int hi = min(lo + 1, 511);
        float w = src - (float)lo;
        float clo = cf[lo];
        return fmaf(cf[hi] - clo, w, clo);
    };
    auto buildZ = [&](int k) -> float2 {
        float ak  = interp(k);
        float akk = interp(8192 - k);
        float fe = 0.5f * (ak + akk);
        float gg = 0.5f * (ak - akk);
        float2 t2 = tw16384(T, k);
        return make_float2(fmaf(t2.y, gg, fe), t2.x * gg);
    };

    // build Z in regs directly at group layout + fused inverse r2/stage4
    {
        int base = t << 4;
        int c = rev9(t);
        float2 a[8], b[8];
#pragma unroll
        for (int r = 0; r < 8; r++) {
            float2 z0 = buildZ(c + (r << 9));            // j=0
            float2 z1 = buildZ(c + (r << 9) + 4096);     // j=1
            a[r] = cadd(z0, z1);
            b[r] = csub(z0, z1);
        }
        float2 w1 = T[512];
        float2 w = w1;
        b[1] = cmulc(b[1], w);
#pragma unroll
        for (int r = 2; r < 8; r++) { w = cmul(w, w1); b[r] = cmulc(b[r], w); }
        bfly8<1>(a);
        bfly8<1>(b);
#pragma unroll
        for (int r = 0; r < 8; r++) {
            buf[IDX(base + 2 * r)]     = a[r];
            buf[IDX(base + 2 * r + 1)] = b[r];
        }
    }
    __syncthreads();
    inv_mid<4>(buf, T, t); __syncthreads();
    inv_mid<7>(buf, T, t); __syncthreads();

    // fused: inverse stage1 -> window -> forward stage1
    const float inv = 1.0f / 8192.0f;
#pragma unroll
    for (int h = 0; h < 2; h++) {
        int bb = t + (h << 9);
        float2 w1 = T[bb];
        float2 v[8];
        v[0] = buf[IDX(bb)];
        float2 w = w1;
        v[1] = cmulc(buf[IDX(bb + 1024)], w);
#pragma unroll
        for (int r = 2; r < 8; r++) { w = cmul(w, w1); v[r] = cmulc(buf[IDX(bb + (r << 10))], w); }
        bfly8<1>(v);
#pragma unroll
        for (int i = 0; i < 8; i++) {
            int n = bb + (i << 10);
            float sx, sy;
            if (n == 0)         { sx = inv;        sy = 2.0f * inv; }
            else if (n < 4096)  { sx = 2.0f * inv; sy = 2.0f * inv; }
            else if (n == 4096) { sx = inv;        sy = 0.0f; }
            else                { sx = 0.0f;       sy = 0.0f; }
            v[i] = make_float2(v[i].x * sx, v[i].y * sy);
        }
        bfly8<-1>(v);
        tw_store(buf, v, bb, 10, w1);
    }
    __syncthreads();
    fwd_mid<7>(buf, T, t); __syncthreads();
    fwd_mid<4>(buf, T, t); __syncthreads();
    fwd_s4_r2(buf, T, t);  __syncthreads();

    // real-spectrum split -> sp[0..8192]
    float2* sp = g_spec + (size_t)d * 8200u;
    for (int k = t + 1; k <= 4095; k += 512) {
        float2 P = buf[IDX(drev(k))], Q = buf[IDX(drev(8192 - k))];
        float2 Fe = make_float2(0.5f * (P.x + Q.x), 0.5f * (P.y - Q.y));
        float2 Fo = make_float2(0.5f * (P.y + Q.y), -0.5f * (P.x - Q.x));
        float2 t2 = tw16384(T, k);
        float2 Xk = cadd(Fe, cmul(t2, Fo));
        float2 cFe = make_float2(Fe.x, -Fe.y);
        float2 cFo = make_float2(Fo.x, -Fo.y);
        float2 nt  = make_float2(-t2.x, t2.y);
        float2 Xkk = cadd(cFe, cmul(nt, cFo));
        sp[k] = Xk;
        sp[8192 - k] = Xkk;
    }
    if (t == 0) {
        float2 Z0 = buf[IDX(0)];
        sp[0]    = make_float2(Z0.x + Z0.y, 0.0f);
        sp[8192] = make_float2(Z0.x - Z0.y, 0.0f);
        float2 Z4 = buf[IDX(1)];             // drev(4096) = 1
        sp[4096] = make_float2(Z4.x, -Z4.y);
    }
}

// Per (b,d): rfft(x row) * spec -> irfft -> first 8192 samples
// Filter is fused into the s4 turnaround with register staging.
__global__ void __launch_bounds__(512, 2) k_conv() {
    extern __shared__ float2 sm[];
    float2* buf = sm;                       // 8704
    float2* T   = sm + 8704;                // 1024
    int bid = blockIdx.x;
    int d = bid & 511;
    int b = bid >> 9;
    int t = threadIdx.x;
    T[t] = g_tw[t];
    T[t + 512] = g_tw[t + 512];
    __syncthreads();

    // forward stage1 fused with gmem load (upper half zero) — ST only
    const float2* xr = (const float2*)(g_xt + ((size_t)(b * 512 + d) << 13));
#pragma unroll
    for (int h = 0; h < 2; h++) {
        int bb = t + (h << 9);
        float2 a[8];
#pragma unroll
        for (int i = 0; i < 4; i++) a[i] = xr[bb + (i << 10)];
        bfly8hz<-1>(a);
        tw_store(buf, a, bb, 10, T[bb]);
    }
    __syncthreads();
    fwd_mid<7>(buf, T, t); __syncthreads();
    fwd_mid<4>(buf, T, t); __syncthreads();

    // ---- fused: fwd s4 + r2 (regs) -> publish -> filter (regs) -> inv r2+s4 ----
    {
        int base = t << 4;
        int c = rev9(t);
        const float2* sp = g_spec + (size_t)d * 8200u;

        // fwd s4 + r2, results kept in P[2r+j]
        float2 e1[8];
#pragma unroll
        for (int i = 0; i < 8; i++) e1[i] = buf[IDX(base + 2 * i + 1)];
        bfly8<-1>(e1);
        {
            float2 w1 = T[512];
            float2 w = w1;
            e1[1] = cmul(e1[1], w);
#pragma unroll
            for (int r = 2; r < 8; r++) { w = cmul(w, w1); e1[r] = cmul(e1[r], w); }
        }
        float2 P[16];
        {
            float2 e0[8];
#pragma unroll
            for (int i = 0; i < 8; i++) e0[i] = buf[IDX(base + 2 * i)];
            bfly8<-1>(e0);
#pragma unroll
            for (int r = 0; r < 8; r++) {
                P[2 * r]     = cadd(e0[r], e1[r]);
                P[2 * r + 1] = csub(e0[r], e1[r]);
            }
        }
        // publish for partner reads
#pragma unroll
        for (int i = 0; i < 16; i++) buf[IDX(base + i)] = P[i];
        __syncthreads();

        // filter each owned coefficient k = c + 512r + 4096j (idx = 2r+j)
#pragma unroll
        for (int idx = 0; idx < 16; idx++) {
            int r = idx >> 1, j = idx & 1;
            int k = c + (r << 9) + (j << 12);
            float2 z;
            if (k == 0) {
                float X0 = P[idx].x + P[idx].y, XN = P[idx].x - P[idx].y;
                float Y0 = X0 * sp[0].x, YN = XN * sp[8192].x;
                z = make_float2(0.5f * (Y0 + YN), 0.5f * (Y0 - YN));
            } else if (k == 4096) {
                float2 X4 = make_float2(P[idx].x, -P[idx].y);
                float2 Y4 = cmul(X4, sp[4096]);
                z = make_float2(Y4.x, -Y4.y);
            } else {
                bool hi = (k > 4096);
                int kb = hi ? (8192 - k) : k;          // low-half member of pair
                float2 A, B;                            // A = val at kb, B = val at 8192-kb
                float2 Qp = buf[IDX(drev(8192 - k))];   // partner value
                if (hi) { A = Qp; B = P[idx]; } else { A = P[idx]; B = Qp; }
                float2 Fe = make_float2(0.5f * (A.x + B.x), 0.5f * (A.y - B.y));
                float2 Fo = make_float2(0.5f * (A.y + B.y), -0.5f * (A.x - B.x));
                float2 t2 = tw16384(T, kb);
                float2 Xk  = cadd(Fe, cmul(t2, Fo));
                float2 cFe = make_float2(Fe.x, -Fe.y);
                float2 cFo = make_float2(Fo.x, -Fo.y);
                float2 nt  = make_float2(-t2.x, t2.y);
                float2 Xkk = cadd(cFe, cmul(nt, cFo));
                float2 Yk  = cmul(Xk,  sp[kb]);
                float2 Ykk = cmul(Xkk, sp[8192 - kb]);
                float2 Fe2 = make_float2(0.5f * (Yk.x + Ykk.x), 0.5f * (Yk.y - Ykk.y));
                float2 hd  = make_float2(0.5f * (Yk.x - Ykk.x), 0.5f * (Yk.y + Ykk.y));
                float2 ct2 = make_float2(t2.x, -t2.y);
                float2 Fo2 = cmul(ct2, hd);
                z = hi ? make_float2(Fe2.x + Fo2.y, -Fe2.y + Fo2.x)
                       : make_float2(Fe2.x - Fo2.y,  Fe2.y + Fo2.x);
            }
            P[idx] = z;
        }
        __syncthreads();   // all partner reads complete before overwrite

        // inverse r2 + s4 in regs
        float2 a[8], bb2[8];
#pragma unroll
        for (int r = 0; r < 8; r++) {
            a[r]   = cadd(P[2 * r], P[2 * r + 1]);
            bb2[r] = csub(P[2 * r], P[2 * r + 1]);
        }
        {
            float2 w1 = T[512];
            float2 w = w1;
            bb2[1] = cmulc(bb2[1], w);
#pragma unroll
            for (int r = 2; r < 8; r++) { w = cmul(w, w1); bb2[r] = cmulc(bb2[r], w); }
        }
        bfly8<1>(a);
        bfly8<1>(bb2);
#pragma unroll
        for (int r = 0; r < 8; r++) {
            buf[IDX(base + 2 * r)]     = a[r];
            buf[IDX(base + 2 * r + 1)] = bb2[r];
        }
    }
    __syncthreads();

    inv_mid<4>(buf, T, t); __syncthreads();
    inv_mid<7>(buf, T, t); __syncthreads();

    // inverse stage1 fused with gmem store (only first half needed) — LD only
    const float inv = 1.0f / 8192.0f;
    float2* yr = (float2*)(g_yt + ((size_t)(b * 512 + d) << 13));
#pragma unroll
    for (int h = 0; h < 2; h++) {
        int bb = t + (h << 9);
        float2 w1 = T[bb];
        float2 v[8];
        v[0] = buf[IDX(bb)];
        float2 w = w1;
        v[1] = cmulc(buf[IDX(bb + 1024)], w);
#pragma unroll
        for (int r = 2; r < 8; r++) { w = cmul(w, w1); v[r] = cmulc(buf[IDX(bb + (r << 10))], w); }
        bfly8<1>(v);
#pragma unroll
        for (int i = 0; i < 4; i++)
            yr[bb + (i << 10)] = make_float2(v[i].x * inv, v[i].y * inv);
    }
}

// ---------------------------------------------------------------------------

extern "C" void kernel_launch(void* const* d_in, const int* in_sizes, int n_in,
                              void* d_out, int out_size) {
    const float* x      = (const float*)d_in[0];
    const float* coeffs = (const float*)d_in[1];
    const float* dc     = (const float*)d_in[2];
    float* out = (float*)d_out;

    size_t smem_c = 9728u * sizeof(float2);            // 77824
    size_t smem_f = smem_c + 512u * sizeof(float);     // 79872
    cudaFuncSetAttribute(k_filter, cudaFuncAttributeMaxDynamicSharedMemorySize, (int)smem_f);
    cudaFuncSetAttribute(k_conv,   cudaFuncAttributeMaxDynamicSharedMemorySize, (int)smem_c);

    k_tw<<<2, 512>>>();
    k_tin<<<dim3(8, 128, 8), dim3(16, 16)>>>(x);
    k_filter<<<512, 512, smem_f>>>(coeffs, dc);
    k_conv<<<4096, 512, smem_c>>>();
    k_tout<<<dim3(8, 128, 8), dim3(16, 16)>>>(out);
}

// round 11
// speedup vs baseline: 1.1798x; 1.1798x over previous
#include <cuda_runtime.h>

// ---------------------------------------------------------------------------
// Causal spectral filter: out = irfft(rfft(x,16384) * spec)[..., :8192, :]
// 8192-pt complex FFT [8,8,8,8,2], in-place smem, 512 threads, 2 blocks/SM.
// R5-proven k_conv/k_filter + float4 64x64 transposes.
// ---------------------------------------------------------------------------

#define IDX(i) ((i) + ((i) >> 4))     // smem pad: conflict-free for all strides

static __device__ float  g_xt[8u * 512u * 8192u];   // x transposed (B,D,N)
static __device__ float  g_yt[8u * 512u * 8192u];   // y transposed (B,D,N)
static __device__ float2 g_spec[512u * 8200u];      // per-channel spectrum (natural k)
static __device__ float2 g_tw[1024];                // W_8192^c, c<1024

__device__ __forceinline__ float2 cadd(float2 a, float2 b) { return make_float2(a.x + b.x, a.y + b.y); }
__device__ __forceinline__ float2 csub(float2 a, float2 b) { return make_float2(a.x - b.x, a.y - b.y); }
__device__ __forceinline__ float2 cmul(float2 a, float2 b) {
    return make_float2(fmaf(a.x, b.x, -a.y * b.y), fmaf(a.x, b.y, a.y * b.x));
}
__device__ __forceinline__ float2 cmulc(float2 a, float2 b) {   // a * conj(b)
    return make_float2(fmaf(a.x, b.x,  a.y * b.y), fmaf(a.y, b.x, -a.x * b.y));
}
template <int S>
__device__ __forceinline__ float2 crot(float2 z) {   // multiply by S*i
    return (S < 0) ? make_float2(z.y, -z.x) : make_float2(-z.y, z.x);
}

// digit-reverse for radices [8,8,8,8,2]: pos of coefficient k after fwd FFT
__device__ __forceinline__ int drev(int k) {
    return ((k & 7) << 10) | (((k >> 3) & 7) << 7) | (((k >> 6) & 7) << 4)
         | (((k >> 9) & 7) << 1) | ((k >> 12) & 1);
}
// 3-digit base-8 reverse of a 9-bit value
__device__ __forceinline__ int rev9(int g) {
    return ((g & 7) << 6) | (g & 56) | ((g >> 6) & 7);
}

// W_16384^k for 0<=k<8192 from the 1024-entry table
__device__ __forceinline__ float2 tw16384(const float2* T, int k) {
    int a = k >> 1;
    float2 w = T[a & 1023];
    int u = (a >> 10) & 3;
    const float S2 = 0.70710678118654752f;
    if (u & 2) w = make_float2(w.y, -w.x);
    if (u & 1) w = cmul(w, make_float2(S2, -S2));
    if (k & 1) w = cmul(w, make_float2(0.99999992646571789f, -3.8349518757139556e-4f));
    return w;
}

template <int SGN>
__device__ __forceinline__ void bfly8(float2 a[8]) {
    const float C0 = 0.70710678118654752f;
    const float2 w81 = make_float2(C0, SGN * C0);
    const float2 w83 = make_float2(-C0, SGN * C0);
    float2 t0 = cadd(a[0], a[4]), t4 = csub(a[0], a[4]);
    float2 t1 = cadd(a[1], a[5]), t5 = csub(a[1], a[5]);
    float2 t2 = cadd(a[2], a[6]), t6 = csub(a[2], a[6]);
    float2 t3 = cadd(a[3], a[7]), t7 = csub(a[3], a[7]);
    float2 E0 = cadd(t0, t2), E2 = csub(t0, t2);
    float2 r6 = crot<SGN>(t6);
    float2 E1 = cadd(t4, r6), E3 = csub(t4, r6);
    float2 O0 = cadd(t1, t3), O2 = csub(t1, t3);
    float2 r7 = crot<SGN>(t7);
    float2 O1 = cadd(t5, r7), O3 = csub(t5, r7);
    float2 m1 = cmul(O1, w81);
    float2 m2 = crot<SGN>(O2);
    float2 m3 = cmul(O3, w83);
    a[0] = cadd(E0, O0); a[4] = csub(E0, O0);
    a[1] = cadd(E1, m1); a[5] = csub(E1, m1);
    a[2] = cadd(E2, m2); a[6] = csub(E2, m2);
    a[3] = cadd(E3, m3); a[7] = csub(E3, m3);
}

// radix-8 butterfly with a[4..7] known zero (only a[0..3] read)
template <int SGN>
__device__ __forceinline__ void bfly8hz(float2 a[8]) {
    const float C0 = 0.70710678118654752f;
    const float2 w81 = make_float2(C0, SGN * C0);
    const float2 w83 = make_float2(-C0, SGN * C0);
    float2 E0 = cadd(a[0], a[2]), E2 = csub(a[0], a[2]);
    float2 r6 = crot<SGN>(a[2]);
    float2 E1 = cadd(a[0], r6), E3 = csub(a[0], r6);
    float2 O0 = cadd(a[1], a[3]), O2 = csub(a[1], a[3]);
    float2 r7 = crot<SGN>(a[3]);
    float2 O1 = cadd(a[1], r7), O3 = csub(a[1], r7);
    float2 m1 = cmul(O1, w81);
    float2 m2 = crot<SGN>(O2);
    float2 m3 = cmul(O3, w83);
    a[0] = cadd(E0, O0); a[4] = csub(E0, O0);
    a[1] = cadd(E1, m1); a[5] = csub(E1, m1);
    a[2] = cadd(E2, m2); a[6] = csub(E2, m2);
    a[3] = cadd(E3, m3); a[7] = csub(E3, m3);
}

// store registers a[] twiddled to positions base + (r<<SH)
__device__ __forceinline__ void tw_store(float2* buf, float2 a[8], int base, int SH, float2 w1) {
    buf[IDX(base)] = a[0];
    float2 w = w1;
    buf[IDX(base + (1 << SH))] = cmul(a[1], w);
#pragma unroll
    for (int r = 2; r < 8; r++) { w = cmul(w, w1); buf[IDX(base + (r << SH))] = cmul(a[r], w); }
}

// ---- stage helpers (512 threads, 2 butterflies each, transient regs) ------

template <int L2S>
__device__ __forceinline__ void fwd_mid(float2* buf, const float2* T, int t) {
#pragma unroll
    for (int h = 0; h < 2; h++) {
        int b = t + (h << 9);
        int j = b & ((1 << L2S) - 1);
        int base = ((b >> L2S) << (L2S + 3)) + j;
        float2 a[8];
#pragma unroll
        for (int i = 0; i < 8; i++) a[i] = buf[IDX(base + (i << L2S))];
        bfly8<-1>(a);
        tw_store(buf, a, base, L2S, T[j << (10 - L2S)]);
    }
}

template <int L2S>
__device__ __forceinline__ void inv_mid(float2* buf, const float2* T, int t) {
#pragma unroll
    for (int h = 0; h < 2; h++) {
        int b = t + (h << 9);
        int j = b & ((1 << L2S) - 1);
        int base = ((b >> L2S) << (L2S + 3)) + j;
        float2 w1 = T[j << (10 - L2S)];
        float2 a[8];
        a[0] = buf[IDX(base)];
        float2 w = w1;
        a[1] = cmulc(buf[IDX(base + (1 << L2S))], w);
#pragma unroll
        for (int r = 2; r < 8; r++) { w = cmul(w, w1); a[r] = cmulc(buf[IDX(base + (r << L2S))], w); }
        bfly8<1>(a);
#pragma unroll
        for (int i = 0; i < 8; i++) buf[IDX(base + (i << L2S))] = a[i];
    }
}

// fwd stage4 + radix-2, fully in-thread (thread t owns group g=t, 16 elems)
__device__ __forceinline__ void fwd_s4_r2(float2* buf, const float2* T, int t) {
    int base = t << 4;
    float2 e1[8];
#pragma unroll
    for (int i = 0; i < 8; i++) e1[i] = buf[IDX(base + 2 * i + 1)];
    bfly8<-1>(e1);
    {
        float2 w1 = T[512];
        float2 w = w1;
        e1[1] = cmul(e1[1], w);
#pragma unroll
        for (int r = 2; r < 8; r++) { w = cmul(w, w1); e1[r] = cmul(e1[r], w); }
    }
    float2 e0[8];
#pragma unroll
    for (int i = 0; i < 8; i++) e0[i] = buf[IDX(base + 2 * i)];
    bfly8<-1>(e0);
#pragma unroll
    for (int r = 0; r < 8; r++) {
        buf[IDX(base + 2 * r)]     = cadd(e0[r], e1[r]);
        buf[IDX(base + 2 * r + 1)] = csub(e0[r], e1[r]);
    }
}

// inverse radix-2 + stage4, fully in-thread
__device__ __forceinline__ void inv_s4_r2(float2* buf, const float2* T, int t) {
    int base = t << 4;
    float2 a[8], b[8];
#pragma unroll
    for (int r = 0; r < 8; r++) {
        float2 z0 = buf[IDX(base + 2 * r)];
        float2 z1 = buf[IDX(base + 2 * r + 1)];
        a[r] = cadd(z0, z1);
        b[r] = csub(z0, z1);
    }
    {
        float2 w1 = T[512];
        float2 w = w1;
        b[1] = cmulc(b[1], w);
#pragma unroll
        for (int r = 2; r < 8; r++) { w = cmul(w, w1); b[r] = cmulc(b[r], w); }
    }
    bfly8<1>(a);
    bfly8<1>(b);
#pragma unroll
    for (int r = 0; r < 8; r++) {
        buf[IDX(base + 2 * r)]     = a[r];
        buf[IDX(base + 2 * r + 1)] = b[r];
    }
}

// ---------------------------------------------------------------------------

__global__ void k_tw() {
    int j = blockIdx.x * blockDim.x + threadIdx.x;
    if (j < 1024) {
        double a = -2.0 * 3.14159265358979323846264338327950288 * (double)j / 8192.0;
        g_tw[j] = make_float2((float)cos(a), (float)sin(a));
    }
}

// x (B,N,D) -> g_xt (B,D,N), 64x64 tiles, float4 both gmem sides
__global__ void __launch_bounds__(256) k_tin(const float* __restrict__ x) {
    __shared__ float s[64][65];
    int b = blockIdx.z;
    int d0 = blockIdx.x << 6, n0 = blockIdx.y << 6;
    int tx = threadIdx.x, ty = threadIdx.y;
    const float* xb = x + (size_t)b * 8192u * 512u;
#pragma unroll
    for (int m = 0; m < 4; m++) {
        int n = n0 + ty + 16 * m;
        float4 v = *(const float4*)&xb[(size_t)n * 512u + d0 + 4 * tx];
        s[4 * tx + 0][ty + 16 * m] = v.x;
        s[4 * tx + 1][ty + 16 * m] = v.y;
        s[4 * tx + 2][ty + 16 * m] = v.z;
        s[4 * tx + 3][ty + 16 * m] = v.w;
    }
    __syncthreads();
    float* xt = g_xt + (size_t)b * 512u * 8192u;
#pragma unroll
    for (int m = 0; m < 4; m++) {
        int dl = ty + 16 * m;
        float4 w = make_float4(s[dl][4 * tx], s[dl][4 * tx + 1],
                               s[dl][4 * tx + 2], s[dl][4 * tx + 3]);
        *(float4*)&xt[(size_t)(d0 + dl) * 8192u + n0 + 4 * tx] = w;
    }
}

// g_yt (B,D,N) -> out (B,N,D), 64x64 tiles, float4 both gmem sides
__global__ void __launch_bounds__(256) k_tout(float* __restrict__ out) {
    __shared__ float s[64][65];
    int b = blockIdx.z;
    int d0 = blockIdx.x << 6, n0 = blockIdx.y << 6;
    int tx = threadIdx.x, ty = threadIdx.y;
    const float* yt = g_yt + (size_t)b * 512u * 8192u;
#pragma unroll
    for (int m = 0; m < 4; m++) {
        int dl = ty + 16 * m;
        float4 v = *(const float4*)&yt[(size_t)(d0 + dl) * 8192u + n0 + 4 * tx];
        s[4 * tx + 0][dl] = v.x;       // s[n_local][d_local]
        s[4 * tx + 1][dl] = v.y;
        s[4 * tx + 2][dl] = v.z;
        s[4 * tx + 3][dl] = v.w;
    }
    __syncthreads();
#pragma unroll
    for (int m = 0; m < 4; m++) {
        int nl = ty + 16 * m;
        float4 w = make_float4(s[nl][4 * tx], s[nl][4 * tx + 1],
                               s[nl][4 * tx + 2], s[nl][4 * tx + 3]);
        *(float4*)&out[((size_t)b * 8192u + n0 + nl) * 512u + d0 + 4 * tx] = w;
    }
}

// Per-channel spectrum build
__global__ void __launch_bounds__(512, 2) k_filter(const float* __restrict__ coeffs,
                                                   const float* __restrict__ dc) {
    extern __shared__ float2 sm[];
    float2* buf = sm;                       // 8704
    float2* T   = sm + 8704;                // 1024
    float*  cf  = (float*)(sm + 9728);      // 512 floats
    int d = blockIdx.x;
    int t = threadIdx.x;
    T[t] = g_tw[t];
    T[t + 512] = g_tw[t + 512];
    cf[t] = coeffs[d * 512 + t];
    float dcv = dc[d];
    __syncthreads();

    auto interp = [&](int k) -> float {
        if (k == 0) return dcv;
        float src = ((float)k - 0.5f) * 0.0625f - 0.5f;
        src = fminf(fmaxf(src, 0.0f), 511.0f);
        int lo = (int)src;
        int hi = min(lo + 1, 511);
        float w = src - (float)lo;
        float clo = cf[lo];
        return fmaf(cf[hi] - clo, w, clo);
    };
    auto buildZ = [&](int k) -> float2 {
        float ak  = interp(k);
        float akk = interp(8192 - k);
        float fe = 0.5f * (ak + akk);
        float gg = 0.5f * (ak - akk);
        float2 t2 = tw16384(T, k);
        return make_float2(fmaf(t2.y, gg, fe), t2.x * gg);
    };

    // build Z in regs directly at group layout + fused inverse r2/stage4
    {
        int base = t << 4;
        int c = rev9(t);
        float2 a[8], b[8];
#pragma unroll
        for (int r = 0; r < 8; r++) {
            float2 z0 = buildZ(c + (r << 9));            // j=0
            float2 z1 = buildZ(c + (r << 9) + 4096);     // j=1
            a[r] = cadd(z0, z1);
            b[r] = csub(z0, z1);
        }
        float2 w1 = T[512];
        float2 w = w1;
        b[1] = cmulc(b[1], w);
#pragma unroll
        for (int r = 2; r < 8; r++) { w = cmul(w, w1); b[r] = cmulc(b[r], w); }
        bfly8<1>(a);
        bfly8<1>(b);
#pragma unroll
        for (int r = 0; r < 8; r++) {
            buf[IDX(base + 2 * r)]     = a[r];
            buf[IDX(base + 2 * r + 1)] = b[r];
        }
    }
    __syncthreads();
    inv_mid<4>(buf, T, t); __syncthreads();
    inv_mid<7>(buf, T, t); __syncthreads();

    // fused: inverse stage1 -> window -> forward stage1
    const float inv = 1.0f / 8192.0f;
#pragma unroll
    for (int h = 0; h < 2; h++) {
        int bb = t + (h << 9);
        float2 w1 = T[bb];
        float2 v[8];
        v[0] = buf[IDX(bb)];
        float2 w = w1;
        v[1] = cmulc(buf[IDX(bb + 1024)], w);
#pragma unroll
        for (int r = 2; r < 8; r++) { w = cmul(w, w1); v[r] = cmulc(buf[IDX(bb + (r << 10))], w); }
        bfly8<1>(v);
#pragma unroll
        for (int i = 0; i < 8; i++) {
            int n = bb + (i << 10);
            float sx, sy;
            if (n == 0)         { sx = inv;        sy = 2.0f * inv; }
            else if (n < 4096)  { sx = 2.0f * inv; sy = 2.0f * inv; }
            else if (n == 4096) { sx = inv;        sy = 0.0f; }
            else                { sx = 0.0f;       sy = 0.0f; }
            v[i] = make_float2(v[i].x * sx, v[i].y * sy);
        }
        bfly8<-1>(v);
        tw_store(buf, v, bb, 10, w1);
    }
    __syncthreads();
    fwd_mid<7>(buf, T, t); __syncthreads();
    fwd_mid<4>(buf, T, t); __syncthreads();
    fwd_s4_r2(buf, T, t);  __syncthreads();

    // real-spectrum split -> sp[0..8192]
    float2* sp = g_spec + (size_t)d * 8200u;
    for (int k = t + 1; k <= 4095; k += 512) {
        float2 P = buf[IDX(drev(k))], Q = buf[IDX(drev(8192 - k))];
        float2 Fe = make_float2(0.5f * (P.x + Q.x), 0.5f * (P.y - Q.y));
        float2 Fo = make_float2(0.5f * (P.y + Q.y), -0.5f * (P.x - Q.x));
        float2 t2 = tw16384(T, k);
        float2 Xk = cadd(Fe, cmul(t2, Fo));
        float2 cFe = make_float2(Fe.x, -Fe.y);
        float2 cFo = make_float2(Fo.x, -Fo.y);
        float2 nt  = make_float2(-t2.x, t2.y);
        float2 Xkk = cadd(cFe, cmul(nt, cFo));
        sp[k] = Xk;
        sp[8192 - k] = Xkk;
    }
    if (t == 0) {
        float2 Z0 = buf[IDX(0)];
        sp[0]    = make_float2(Z0.x + Z0.y, 0.0f);
        sp[8192] = make_float2(Z0.x - Z0.y, 0.0f);
        float2 Z4 = buf[IDX(1)];             // drev(4096) = 1
        sp[4096] = make_float2(Z4.x, -Z4.y);
    }
}

// Per (b,d): rfft(x row) * spec -> irfft -> first 8192 samples (R5-proven)
__global__ void __launch_bounds__(512, 2) k_conv() {
    extern __shared__ float2 sm[];
    float2* buf = sm;                       // 8704
    float2* T   = sm + 8704;                // 1024
    int bid = blockIdx.x;
    int d = bid & 511;
    int b = bid >> 9;
    int t = threadIdx.x;
    T[t] = g_tw[t];
    T[t + 512] = g_tw[t + 512];
    __syncthreads();

    // forward stage1 fused with gmem load (upper half zero) — ST only
    const float2* xr = (const float2*)(g_xt + ((size_t)(b * 512 + d) << 13));
#pragma unroll
    for (int h = 0; h < 2; h++) {
        int bb = t + (h << 9);
        float2 a[8];
#pragma unroll
        for (int i = 0; i < 4; i++) a[i] = xr[bb + (i << 10)];
        bfly8hz<-1>(a);
        tw_store(buf, a, bb, 10, T[bb]);
    }
    __syncthreads();
    fwd_mid<7>(buf, T, t); __syncthreads();
    fwd_mid<4>(buf, T, t); __syncthreads();
    fwd_s4_r2(buf, T, t);  __syncthreads();

    // pointwise filter on conjugate pairs (in-place, pair-partitioned)
    const float2* sp = g_spec + (size_t)d * 8200u;
    for (int k = t + 1; k <= 4095; k += 512) {
        int kk = 8192 - k;
        int p1 = IDX(drev(k)), p2 = IDX(drev(kk));
        float2 P = buf[p1], Q = buf[p2];
        float2 Fe = make_float2(0.5f * (P.x + Q.x), 0.5f * (P.y - Q.y));
        float2 Fo = make_float2(0.5f * (P.y + Q.y), -0.5f * (P.x - Q.x));
        float2 t2 = tw16384(T, k);
        float2 Xk  = cadd(Fe, cmul(t2, Fo));
        float2 cFe = make_float2(Fe.x, -Fe.y);
        float2 cFo = make_float2(Fo.x, -Fo.y);
        float2 nt  = make_float2(-t2.x, t2.y);
        float2 Xkk = cadd(cFe, cmul(nt, cFo));
        float2 Yk  = cmul(Xk,  sp[k]);
        float2 Ykk = cmul(Xkk, sp[kk]);
        float2 Fe2 = make_float2(0.5f * (Yk.x + Ykk.x), 0.5f * (Yk.y - Ykk.y));
        float2 hd  = make_float2(0.5f * (Yk.x - Ykk.x), 0.5f * (Yk.y + Ykk.y));
        float2 ct2 = make_float2(t2.x, -t2.y);
        float2 Fo2 = cmul(ct2, hd);
        buf[p1] = make_float2(Fe2.x - Fo2.y,  Fe2.y + Fo2.x);
        buf[p2] = make_float2(Fe2.x + Fo2.y, -Fe2.y + Fo2.x);
    }
    if (t == 0) {
        float2 Z0 = buf[IDX(0)];
        float X0 = Z0.x + Z0.y;
        float XN = Z0.x - Z0.y;
        float Y0 = X0 * sp[0].x;
        float YN = XN * sp[8192].x;
        buf[IDX(0)] = make_float2(0.5f * (Y0 + YN), 0.5f * (Y0 - YN));
        float2 Z4 = buf[IDX(1)];             // drev(4096) = 1
        float2 X4 = make_float2(Z4.x, -Z4.y);
        float2 Y4 = cmul(X4, sp[4096]);
        buf[IDX(1)] = make_float2(Y4.x, -Y4.y);
    }
    __syncthreads();

    inv_s4_r2(buf, T, t);  __syncthreads();
    inv_mid<4>(buf, T, t); __syncthreads();
    inv_mid<7>(buf, T, t); __syncthreads();

    // inverse stage1 fused with gmem store (only first half needed) — LD only
    const float inv = 1.0f / 8192.0f;
    float2* yr = (float2*)(g_yt + ((size_t)(b * 512 + d) << 13));
#pragma unroll
    for (int h = 0; h < 2; h++) {
        int bb = t + (h << 9);
        float2 w1 = T[bb];
        float2 v[8];
        v[0] = buf[IDX(bb)];
        float2 w = w1;
        v[1] = cmulc(buf[IDX(bb + 1024)], w);
#pragma unroll
        for (int r = 2; r < 8; r++) { w = cmul(w, w1); v[r] = cmulc(buf[IDX(bb + (r << 10))], w); }
        bfly8<1>(v);
#pragma unroll
        for (int i = 0; i < 4; i++)
            yr[bb + (i << 10)] = make_float2(v[i].x * inv, v[i].y * inv);
    }
}

// ---------------------------------------------------------------------------

extern "C" void kernel_launch(void* const* d_in, const int* in_sizes, int n_in,
                              void* d_out, int out_size) {
    const float* x      = (const float*)d_in[0];
    const float* coeffs = (const float*)d_in[1];
    const float* dc     = (const float*)d_in[2];
    float* out = (float*)d_out;

    size_t smem_c = 9728u * sizeof(float2);            // 77824
    size_t smem_f = smem_c + 512u * sizeof(float);     // 79872
    cudaFuncSetAttribute(k_filter, cudaFuncAttributeMaxDynamicSharedMemorySize, (int)smem_f);
    cudaFuncSetAttribute(k_conv,   cudaFuncAttributeMaxDynamicSharedMemorySize, (int)smem_c);

    k_tw<<<2, 512>>>();
    k_tin<<<dim3(8, 128, 8), dim3(16, 16)>>>(x);
    k_filter<<<512, 512, smem_f>>>(coeffs, dc);
    k_conv<<<4096, 512, smem_c>>>();
    k_tout<<<dim3(8, 128, 8), dim3(16, 16)>>>(out);
}